// round 8
// baseline (speedup 1.0000x reference)
#include <cuda_runtime.h>

#define EPS 1e-5f

// ---------------- device scratch ----------------
__device__ float g_Hmk[1024 * 512];    // [b][c:8][l:64]
__device__ float g_Hml[1024 * 256];    // [b][c:8][k:32]
__device__ float g_A1[1024 * 4096];    // layer1 AP post-relu RAW [b][o:64][l:64]
__device__ float g_U1m[1024 * 64];     // mean over k of layer1 UE post-relu RAW [b][c:64]
__device__ float g_M0A[1024 * 64];     // mean over l of layer0 AP relu RAW [b][o:64]
__device__ float g_M0U[1024 * 64];     // mean over k of layer0 UE relu RAW [b][o:64]
__device__ float g_stats[512];         // L0: apS,apSS,ueS,ueSS @0,64,128,192; L1 @256..
__device__ float g_TQa[4096];          // 2*Qh1[0]^T [c][o]
__device__ float g_TQu[4096];          // 2*Qh1[2]^T
__device__ float g_Q2a_oc[4096];       // 2*Qh1[1] [o][c]  (original layout, coalesced dot)
__device__ float g_Q2u_oc[4096];       // 2*Qh1[3] [o][c]
__device__ float g_TPa[512];           // 0.1*Ph1[0]^T [c:8][o:64]
__device__ float g_TPu[512];
__device__ float g_TQo[2048];          // 2*Qo[0]^T [c:64][k:32]
__device__ float g_Qo2_kc[2048];       // 2*Qo[1] [k][c]   (original layout, coalesced dot)
__device__ float g_TPo[256];           // 0.1*Po[0]^T [c:8][k:32]

static __device__ __forceinline__ float4 ld4(const float* p) { return *reinterpret_cast<const float4*>(p); }
static __device__ __forceinline__ float2 ld2(const float* p) { return *reinterpret_cast<const float2*>(p); }
static __device__ __forceinline__ void st4(float* p, float4 v) { *reinterpret_cast<float4*>(p) = v; }

// ---------------- K0 (16 blocks): zero stats + weight prep ----------------
__global__ void __launch_bounds__(256) k0_prep(const float* __restrict__ Qh,
                                               const float* __restrict__ Ph,
                                               const float* __restrict__ Qo,
                                               const float* __restrict__ Po) {
    int gt = blockIdx.x * 256 + threadIdx.x;   // 0..4095
    if (gt < 512) g_stats[gt] = 0.f;
    {
        int c = gt >> 6, o = gt & 63;
        g_TQa[gt] = 2.f * Qh[4 * 4096 + o * 64 + c];
        g_TQu[gt] = 2.f * Qh[6 * 4096 + o * 64 + c];
        g_Q2a_oc[gt] = 2.f * Qh[5 * 4096 + gt];
        g_Q2u_oc[gt] = 2.f * Qh[7 * 4096 + gt];
    }
    if (gt < 512) {
        int c = gt >> 6, o = gt & 63;
        g_TPa[gt] = 0.1f * Ph[1024 + o * 8 + c];
        g_TPu[gt] = 0.1f * Ph[1536 + o * 8 + c];
    }
    if (gt < 2048) {
        int c = gt >> 5, k = gt & 31;
        g_TQo[gt] = 2.f * Qo[k * 64 + c];
        g_Qo2_kc[gt] = 2.f * Qo[2048 + gt];
    }
    if (gt < 256) {
        int c = gt >> 5, k = gt & 31;
        g_TPo[gt] = 0.1f * Po[k * 8 + c];
    }
}

// ---------------- K1: single pass over H -> Hmk/Hml + layer0 stats + raw means ----------------
struct SK1 {
    float S[8][64 * 33];    // [c][l*33+k]
    float Hmk[512];
    float Hml[256];
};

__global__ void __launch_bounds__(256) k1_l0(const float* __restrict__ Hr,
                                             const float* __restrict__ Hi,
                                             const float* __restrict__ Ph) {
    extern __shared__ __align__(16) char sraw1[];
    SK1& S = *reinterpret_cast<SK1*>(sraw1);
    int b = blockIdx.x, t = threadIdx.x, w = t >> 5, lane = t & 31;

    const float4* hr4 = reinterpret_cast<const float4*>(Hr) + (size_t)b * 2048;
    const float4* hi4 = reinterpret_cast<const float4*>(Hi) + (size_t)b * 2048;
#pragma unroll
    for (int i = 0; i < 8; i++) {
        int l = i * 8 + w;
        float4 r = hr4[l * 32 + lane];
        float4 m = hi4[l * 32 + lane];
        int base = l * 33 + lane;
        S.S[0][base] = r.x; S.S[1][base] = r.y; S.S[2][base] = r.z; S.S[3][base] = r.w;
        S.S[4][base] = m.x; S.S[5][base] = m.y; S.S[6][base] = m.z; S.S[7][base] = m.w;
    }
    __syncthreads();

#pragma unroll
    for (int p = 0; p < 2; p++) {
        int idx = t + p * 256;
        int c = idx >> 6, l = idx & 63;
        float s = 0.f;
#pragma unroll
        for (int k = 0; k < 32; k++) s += S.S[c][l * 33 + k];
        float v = s * (1.f / 32.f);
        S.Hmk[idx] = v;
        g_Hmk[(size_t)b * 512 + idx] = v;
    }
    {
        int c = t >> 5, k = t & 31;
        float s = 0.f;
#pragma unroll
        for (int l = 0; l < 64; l++) s += S.S[c][l * 33 + k];
        float v = s * (1.f / 64.f);
        S.Hml[t] = v;
        g_Hml[(size_t)b * 256 + t] = v;
    }
    __syncthreads();

    // layer0 stats + per-b raw means (A inputs zero => relu(0.1*P0 @ Hmean))
    int o = t >> 2, q = t & 3;
    float pa[8], pu[8];
#pragma unroll
    for (int c = 0; c < 8; c++) {
        pa[c] = 0.1f * Ph[o * 8 + c];
        pu[c] = 0.1f * Ph[512 + o * 8 + c];
    }
    float ps = 0.f, pss = 0.f;
#pragma unroll
    for (int j = 0; j < 16; j++) {
        int l = q * 16 + j;
        float v = 0.f;
#pragma unroll
        for (int c = 0; c < 8; c++) v += pa[c] * S.Hmk[c * 64 + l];
        v = fmaxf(v, 0.f);
        ps += v; pss += v * v;
    }
    ps += __shfl_xor_sync(0xffffffffu, ps, 1);  ps += __shfl_xor_sync(0xffffffffu, ps, 2);
    pss += __shfl_xor_sync(0xffffffffu, pss, 1); pss += __shfl_xor_sync(0xffffffffu, pss, 2);
    if (q == 0) {
        atomicAdd(&g_stats[o], ps); atomicAdd(&g_stats[64 + o], pss);
        g_M0A[(size_t)b * 64 + o] = ps * (1.f / 64.f);
    }

    float us = 0.f, uss = 0.f;
#pragma unroll
    for (int j = 0; j < 8; j++) {
        int k = q * 8 + j;
        float v = 0.f;
#pragma unroll
        for (int c = 0; c < 8; c++) v += pu[c] * S.Hml[c * 32 + k];
        v = fmaxf(v, 0.f);
        us += v; uss += v * v;
    }
    us += __shfl_xor_sync(0xffffffffu, us, 1);  us += __shfl_xor_sync(0xffffffffu, us, 2);
    uss += __shfl_xor_sync(0xffffffffu, uss, 1); uss += __shfl_xor_sync(0xffffffffu, uss, 2);
    if (q == 0) {
        atomicAdd(&g_stats[128 + o], us); atomicAdd(&g_stats[192 + o], uss);
        g_M0U[(size_t)b * 64 + o] = us * (1.f / 32.f);
    }
}

// ---------------- K2: recompute layer0 (lazy BN), layer1 GEMMs (inline bias), relu, stats ----------------
struct __align__(16) SK2 {
    float AP[4096], UE[2048];
    float Pa[512], Pu[512], P0a[512], P0u[512];
    float Hmk[512], Hml[256];
    float ScA[64], ShA[64], ScU[64], ShU[64];
    float MA[64], MU[64];
};

__global__ void __launch_bounds__(256) k2_full(const float* __restrict__ Ph,
                                               const float* __restrict__ gamma,
                                               const float* __restrict__ beta) {
    extern __shared__ __align__(16) char sraw[];
    SK2& S = *reinterpret_cast<SK2*>(sraw);
    int b = blockIdx.x, t = threadIdx.x;

    // phase 0: BN coefs + normalized layer-0 means + staging
    if (t < 64) {
        float m = g_stats[t] * (1.f / 65536.f);
        float v = g_stats[64 + t] * (1.f / 65536.f) - m * m;
        float sc = gamma[t] * rsqrtf(v + EPS);
        float sha = beta[t] - m * sc;
        S.ScA[t] = sc; S.ShA[t] = sha;
        float mu = g_stats[128 + t] * (1.f / 32768.f);
        float vu = g_stats[192 + t] * (1.f / 32768.f) - mu * mu;
        float su = gamma[t] * rsqrtf(vu + EPS);
        float shu = beta[t] - mu * su;
        S.ScU[t] = su; S.ShU[t] = shu;
        S.MA[t] = g_M0A[(size_t)b * 64 + t] * sc + sha;   // mean of BN'd layer0 AP
        S.MU[t] = g_M0U[(size_t)b * 64 + t] * su + shu;   // mean of BN'd layer0 UE
    }
    for (int i = t; i < 512; i += 256) {
        S.Pa[i] = g_TPa[i]; S.Pu[i] = g_TPu[i];
        S.P0a[i] = 0.1f * Ph[i]; S.P0u[i] = 0.1f * Ph[512 + i];
        S.Hmk[i] = g_Hmk[(size_t)b * 512 + i];
    }
    S.Hml[t] = g_Hml[(size_t)b * 256 + t];
    __syncthreads();   // barrier 1

    // phase 1: recompute normalized layer0 outputs
    {
        int l = t & 63, og = t >> 6;
#pragma unroll
        for (int j = 0; j < 16; j++) {
            int o = og * 16 + j;
            float r = 0.f;
#pragma unroll
            for (int c = 0; c < 8; c++) r += S.P0a[o * 8 + c] * S.Hmk[c * 64 + l];
            S.AP[o * 64 + l] = fmaxf(r, 0.f) * S.ScA[o] + S.ShA[o];
        }
        int k = t & 31, og2 = t >> 5;
#pragma unroll
        for (int j = 0; j < 8; j++) {
            int o = og2 * 8 + j;
            float r = 0.f;
#pragma unroll
            for (int c = 0; c < 8; c++) r += S.P0u[o * 8 + c] * S.Hml[c * 32 + k];
            S.UE[o * 32 + k] = fmaxf(r, 0.f) * S.ScU[o] + S.ShU[o];
        }
    }
    __syncthreads();   // barrier 2

    // AP GEMM: 4(o) x 4(l) tile; bias inline via half-warp shuffle (coalesced [o][c] reads)
    int o0 = (t >> 4) * 4, l0 = (t & 15) * 4;
    int hw = t & 15;
    float acc[4][4];
#pragma unroll
    for (int i = 0; i < 4; i++) {
        float s = 0.f;
#pragma unroll
        for (int j = 0; j < 4; j++) {
            int c = hw * 4 + j;
            s += g_Q2a_oc[(o0 + i) * 64 + c] * S.MU[c];
        }
        s += __shfl_xor_sync(0xffffffffu, s, 1);
        s += __shfl_xor_sync(0xffffffffu, s, 2);
        s += __shfl_xor_sync(0xffffffffu, s, 4);
        s += __shfl_xor_sync(0xffffffffu, s, 8);
#pragma unroll
        for (int j = 0; j < 4; j++) acc[i][j] = s;
    }
#pragma unroll
    for (int c = 0; c < 8; c++) {
        float4 p = ld4(&S.Pa[c * 64 + o0]);
        float4 h = ld4(&S.Hmk[c * 64 + l0]);
        acc[0][0] += p.x * h.x; acc[0][1] += p.x * h.y; acc[0][2] += p.x * h.z; acc[0][3] += p.x * h.w;
        acc[1][0] += p.y * h.x; acc[1][1] += p.y * h.y; acc[1][2] += p.y * h.z; acc[1][3] += p.y * h.w;
        acc[2][0] += p.z * h.x; acc[2][1] += p.z * h.y; acc[2][2] += p.z * h.z; acc[2][3] += p.z * h.w;
        acc[3][0] += p.w * h.x; acc[3][1] += p.w * h.y; acc[3][2] += p.w * h.z; acc[3][3] += p.w * h.w;
    }
#pragma unroll
    for (int c = 0; c < 64; c++) {
        float4 qv = ld4(&g_TQa[c * 64 + o0]);
        float4 av = ld4(&S.AP[c * 64 + l0]);
        acc[0][0] += qv.x * av.x; acc[0][1] += qv.x * av.y; acc[0][2] += qv.x * av.z; acc[0][3] += qv.x * av.w;
        acc[1][0] += qv.y * av.x; acc[1][1] += qv.y * av.y; acc[1][2] += qv.y * av.z; acc[1][3] += qv.y * av.w;
        acc[2][0] += qv.z * av.x; acc[2][1] += qv.z * av.y; acc[2][2] += qv.z * av.z; acc[2][3] += qv.z * av.w;
        acc[3][0] += qv.w * av.x; acc[3][1] += qv.w * av.y; acc[3][2] += qv.w * av.z; acc[3][3] += qv.w * av.w;
    }

    // UE GEMM: 2(o) x 4(k) tile; bias inline via 8-lane shuffle (coalesced [o][c] reads)
    int ou = (t >> 3) * 2, kq = (t & 7) * 4;
    int qw = t & 7;
    float au[2][4];
#pragma unroll
    for (int i = 0; i < 2; i++) {
        float s = 0.f;
#pragma unroll
        for (int j = 0; j < 8; j++) {
            int c = qw * 8 + j;
            s += g_Q2u_oc[(ou + i) * 64 + c] * S.MA[c];
        }
        s += __shfl_xor_sync(0xffffffffu, s, 1);
        s += __shfl_xor_sync(0xffffffffu, s, 2);
        s += __shfl_xor_sync(0xffffffffu, s, 4);
#pragma unroll
        for (int j = 0; j < 4; j++) au[i][j] = s;
    }
#pragma unroll
    for (int c = 0; c < 8; c++) {
        float2 p = ld2(&S.Pu[c * 64 + ou]);
        float4 h = ld4(&S.Hml[c * 32 + kq]);
        au[0][0] += p.x * h.x; au[0][1] += p.x * h.y; au[0][2] += p.x * h.z; au[0][3] += p.x * h.w;
        au[1][0] += p.y * h.x; au[1][1] += p.y * h.y; au[1][2] += p.y * h.z; au[1][3] += p.y * h.w;
    }
#pragma unroll
    for (int c = 0; c < 64; c++) {
        float2 qv = ld2(&g_TQu[c * 64 + ou]);
        float4 uv = ld4(&S.UE[c * 32 + kq]);
        au[0][0] += qv.x * uv.x; au[0][1] += qv.x * uv.y; au[0][2] += qv.x * uv.z; au[0][3] += qv.x * uv.w;
        au[1][0] += qv.y * uv.x; au[1][1] += qv.y * uv.y; au[1][2] += qv.y * uv.z; au[1][3] += qv.y * uv.w;
    }

    // epilogue in registers: relu, direct A1 store, shuffle-group stats
    float sA[4], sAS[4];
#pragma unroll
    for (int i = 0; i < 4; i++) {
        float r0 = fmaxf(acc[i][0], 0.f), r1 = fmaxf(acc[i][1], 0.f);
        float r2 = fmaxf(acc[i][2], 0.f), r3 = fmaxf(acc[i][3], 0.f);
        st4(&g_A1[(size_t)b * 4096 + (o0 + i) * 64 + l0], make_float4(r0, r1, r2, r3));
        sA[i] = r0 + r1 + r2 + r3;
        sAS[i] = r0 * r0 + r1 * r1 + r2 * r2 + r3 * r3;
    }
#pragma unroll
    for (int m = 1; m < 16; m <<= 1) {
#pragma unroll
        for (int i = 0; i < 4; i++) {
            sA[i] += __shfl_xor_sync(0xffffffffu, sA[i], m);
            sAS[i] += __shfl_xor_sync(0xffffffffu, sAS[i], m);
        }
    }
    if ((t & 15) == 0) {
#pragma unroll
        for (int i = 0; i < 4; i++) {
            atomicAdd(&g_stats[256 + o0 + i], sA[i]);
            atomicAdd(&g_stats[320 + o0 + i], sAS[i]);
        }
    }

    float sU[2], sUS[2];
#pragma unroll
    for (int i = 0; i < 2; i++) {
        float r0 = fmaxf(au[i][0], 0.f), r1 = fmaxf(au[i][1], 0.f);
        float r2 = fmaxf(au[i][2], 0.f), r3 = fmaxf(au[i][3], 0.f);
        sU[i] = r0 + r1 + r2 + r3;
        sUS[i] = r0 * r0 + r1 * r1 + r2 * r2 + r3 * r3;
    }
#pragma unroll
    for (int m = 1; m < 8; m <<= 1) {
#pragma unroll
        for (int i = 0; i < 2; i++) {
            sU[i] += __shfl_xor_sync(0xffffffffu, sU[i], m);
            sUS[i] += __shfl_xor_sync(0xffffffffu, sUS[i], m);
        }
    }
    if ((t & 7) == 0) {
#pragma unroll
        for (int i = 0; i < 2; i++) {
            atomicAdd(&g_stats[384 + ou + i], sU[i]);
            atomicAdd(&g_stats[448 + ou + i], sUS[i]);
            g_U1m[(size_t)b * 64 + ou + i] = sU[i] * (1.f / 32.f);
        }
    }
}

// ---------------- K3: output GEMM (inline warp bias), warp norm, fused Vhat stream ----------------
__global__ void __launch_bounds__(256) k3_fused(const float* __restrict__ gamma,
                                                const float* __restrict__ beta,
                                                const float* __restrict__ Vh,
                                                float* __restrict__ out) {
    __shared__ float sAP[4096];          // normalized layer1 AP [c][l]
    __shared__ float sPo[256];
    __shared__ float sHmk[512];
    __shared__ float sV[32 * 65];        // normalized Phat^T [k][l], padded
    __shared__ float sScA[64], sShA[64], sMU[64];
    int b = blockIdx.x, t = threadIdx.x;
    int ko = (t >> 5) * 4, lo = (t & 31) * 2, lane = t & 31;

    // phase 0: A1 register prefetch, BN coefs, staging
    float a_raw[16];
#pragma unroll
    for (int j = 0; j < 16; j++) a_raw[j] = g_A1[(size_t)b * 4096 + t + j * 256];

    if (t < 64) {
        float m = g_stats[256 + t] * (1.f / 65536.f);
        float v = g_stats[320 + t] * (1.f / 65536.f) - m * m;
        float sc = gamma[64 + t] * rsqrtf(v + EPS);
        sScA[t] = sc; sShA[t] = beta[64 + t] - m * sc;
        float mu = g_stats[384 + t] * (1.f / 32768.f);
        float vu = g_stats[448 + t] * (1.f / 32768.f) - mu * mu;
        float su = gamma[64 + t] * rsqrtf(vu + EPS);
        sMU[t] = g_U1m[(size_t)b * 64 + t] * su + (beta[64 + t] - mu * su);
    }
    sPo[t] = g_TPo[t];
    for (int i = t; i < 512; i += 256) sHmk[i] = g_Hmk[(size_t)b * 512 + i];
    __syncthreads();   // barrier 1

    // phase 1: normalized AP staging + bias via full-warp shuffle (coalesced [k][c] reads)
#pragma unroll
    for (int j = 0; j < 16; j++) {
        int i = t + j * 256;
        int c = i >> 6;
        sAP[i] = a_raw[j] * sScA[c] + sShA[c];
    }
    float m0 = sMU[2 * lane], m1 = sMU[2 * lane + 1];
    float bias[4];
#pragma unroll
    for (int i = 0; i < 4; i++) {
        float2 q = ld2(&g_Qo2_kc[(ko + i) * 64 + 2 * lane]);
        float s = q.x * m0 + q.y * m1;
        s += __shfl_xor_sync(0xffffffffu, s, 1);
        s += __shfl_xor_sync(0xffffffffu, s, 2);
        s += __shfl_xor_sync(0xffffffffu, s, 4);
        s += __shfl_xor_sync(0xffffffffu, s, 8);
        s += __shfl_xor_sync(0xffffffffu, s, 16);
        bias[i] = s;
    }
    __syncthreads();   // barrier 2

    // GEMM 32(k) x 64(l) x 72: thread tile 4(k) x 2(l)
    float acc[4][2];
#pragma unroll
    for (int i = 0; i < 4; i++) { acc[i][0] = bias[i]; acc[i][1] = bias[i]; }
#pragma unroll
    for (int c = 0; c < 8; c++) {
        float4 p = ld4(&sPo[c * 32 + ko]);
        float h0 = sHmk[c * 64 + lo], h1 = sHmk[c * 64 + lo + 1];
        acc[0][0] += p.x * h0; acc[0][1] += p.x * h1;
        acc[1][0] += p.y * h0; acc[1][1] += p.y * h1;
        acc[2][0] += p.z * h0; acc[2][1] += p.z * h1;
        acc[3][0] += p.w * h0; acc[3][1] += p.w * h1;
    }
#pragma unroll
    for (int c = 0; c < 64; c++) {
        float4 qv = ld4(&g_TQo[c * 32 + ko]);
        float2 a = ld2(&sAP[c * 64 + lo]);
        acc[0][0] += qv.x * a.x; acc[0][1] += qv.x * a.y;
        acc[1][0] += qv.y * a.x; acc[1][1] += qv.y * a.y;
        acc[2][0] += qv.z * a.x; acc[2][1] += qv.z * a.y;
        acc[3][0] += qv.w * a.x; acc[3][1] += qv.w * a.y;
    }

    // per-k L2 norm over l: warp-local shuffle reduce; fold fac into sV store
#pragma unroll
    for (int i = 0; i < 4; i++) {
        float ss = acc[i][0] * acc[i][0] + acc[i][1] * acc[i][1];
        ss += __shfl_xor_sync(0xffffffffu, ss, 1);
        ss += __shfl_xor_sync(0xffffffffu, ss, 2);
        ss += __shfl_xor_sync(0xffffffffu, ss, 4);
        ss += __shfl_xor_sync(0xffffffffu, ss, 8);
        ss += __shfl_xor_sync(0xffffffffu, ss, 16);
        float fac = 8.f * rsqrtf(ss);               // sqrt(L)=8
        sV[(ko + i) * 65 + lo] = acc[i][0] * fac;
        sV[(ko + i) * 65 + lo + 1] = acc[i][1] * fac;
    }
    __syncthreads();   // barrier 3

    // fused stream: out[b,l,k,:] = Vhat[b,l,k,:] * Phat[b,l,k]
    const float4* v4 = reinterpret_cast<const float4*>(Vh) + (size_t)b * 2048;
    float4* o4 = reinterpret_cast<float4*>(out) + (size_t)b * 2048;
#pragma unroll
    for (int j = 0; j < 8; j++) {
        int i = t + j * 256;
        int l = i >> 5, k = i & 31;
        float pf = sV[k * 65 + l];
        float4 v = v4[i];
        v.x *= pf; v.y *= pf; v.z *= pf; v.w *= pf;
        o4[i] = v;
    }
}

// ---------------- host ----------------
extern "C" void kernel_launch(void* const* d_in, const int* in_sizes, int n_in,
                              void* d_out, int out_size) {
    (void)in_sizes; (void)n_in; (void)out_size;
    const float* Hr = (const float*)d_in[0];
    const float* Hi = (const float*)d_in[1];
    const float* Vh = (const float*)d_in[2];
    const float* Qh = (const float*)d_in[3];
    const float* Ph = (const float*)d_in[4];
    const float* Qo = (const float*)d_in[5];
    const float* Po = (const float*)d_in[6];
    const float* gamma = (const float*)d_in[7];
    const float* beta = (const float*)d_in[8];

    static int attr_done = 0;
    if (!attr_done) {
        cudaFuncSetAttribute(k1_l0, cudaFuncAttributeMaxDynamicSharedMemorySize, (int)sizeof(SK1));
        cudaFuncSetAttribute(k2_full, cudaFuncAttributeMaxDynamicSharedMemorySize, (int)sizeof(SK2));
        attr_done = 1;
    }

    k0_prep<<<16, 256>>>(Qh, Ph, Qo, Po);
    k1_l0<<<1024, 256, sizeof(SK1)>>>(Hr, Hi, Ph);
    k2_full<<<1024, 256, sizeof(SK2)>>>(Ph, gamma, beta);
    k3_fused<<<1024, 256>>>(gamma, beta, Vh, (float*)d_out);
}

// round 9
// speedup vs baseline: 1.0683x; 1.0683x over previous
#include <cuda_runtime.h>

#define EPS 1e-5f

// ---------------- device scratch ----------------
__device__ float g_Hmk[1024 * 512];    // [b][c:8][l:64]
__device__ float g_Hml[1024 * 256];    // [b][c:8][k:32]
__device__ float g_A1[1024 * 4096];    // layer1 AP post-relu RAW [b][o:64][l:64]
__device__ float g_U1m[1024 * 64];     // mean over k of layer1 UE post-relu RAW [b][c:64]
__device__ float g_stats[512];         // L0: apS,apSS,ueS,ueSS @0,64,128,192; L1 @256..
__device__ float g_TQa[4096];          // 2*Qh1[0]^T [c][o]
__device__ float g_TQu[4096];          // 2*Qh1[2]^T
__device__ float g_TQ2a[4096];         // 2*Qh1[1]^T [c][o]
__device__ float g_TQ2u[4096];         // 2*Qh1[3]^T
__device__ float g_TPa[512];           // 0.1*Ph1[0]^T [c:8][o:64]
__device__ float g_TPu[512];
__device__ float g_TQo[2048];          // 2*Qo[0]^T [c:64][k:32]
__device__ float g_TQo2[2048];         // 2*Qo[1]^T [c:64][k:32]
__device__ float g_TPo[256];           // 0.1*Po[0]^T [c:8][k:32]

static __device__ __forceinline__ float4 ld4(const float* p) { return *reinterpret_cast<const float4*>(p); }
static __device__ __forceinline__ float2 ld2(const float* p) { return *reinterpret_cast<const float2*>(p); }
static __device__ __forceinline__ void st4(float* p, float4 v) { *reinterpret_cast<float4*>(p) = v; }

// ---------------- K0 (16 blocks): zero stats + transpose/pre-scale weights ----------------
__global__ void __launch_bounds__(256) k0_prep(const float* __restrict__ Qh,
                                               const float* __restrict__ Ph,
                                               const float* __restrict__ Qo,
                                               const float* __restrict__ Po) {
    int gt = blockIdx.x * 256 + threadIdx.x;   // 0..4095
    if (gt < 512) g_stats[gt] = 0.f;
    {
        int c = gt >> 6, o = gt & 63;
        g_TQa[gt]  = 2.f * Qh[4 * 4096 + o * 64 + c];
        g_TQ2a[gt] = 2.f * Qh[5 * 4096 + o * 64 + c];
        g_TQu[gt]  = 2.f * Qh[6 * 4096 + o * 64 + c];
        g_TQ2u[gt] = 2.f * Qh[7 * 4096 + o * 64 + c];
    }
    if (gt < 512) {
        int c = gt >> 6, o = gt & 63;
        g_TPa[gt] = 0.1f * Ph[1024 + o * 8 + c];
        g_TPu[gt] = 0.1f * Ph[1536 + o * 8 + c];
    }
    if (gt < 2048) {
        int c = gt >> 5, k = gt & 31;
        g_TQo[gt]  = 2.f * Qo[k * 64 + c];
        g_TQo2[gt] = 2.f * Qo[2048 + k * 64 + c];
    }
    if (gt < 256) {
        int c = gt >> 5, k = gt & 31;
        g_TPo[gt] = 0.1f * Po[k * 8 + c];
    }
}

// ---------------- K1: single pass over H -> Hmk/Hml + layer0 stats ----------------
struct SK1 {
    float S[8][64 * 33];    // [c][l*33+k]
    float Hmk[512];
    float Hml[256];
};

__global__ void __launch_bounds__(256, 3) k1_l0(const float* __restrict__ Hr,
                                                const float* __restrict__ Hi,
                                                const float* __restrict__ Ph) {
    extern __shared__ __align__(16) char sraw1[];
    SK1& S = *reinterpret_cast<SK1*>(sraw1);
    int b = blockIdx.x, t = threadIdx.x, w = t >> 5, lane = t & 31;

    const float4* hr4 = reinterpret_cast<const float4*>(Hr) + (size_t)b * 2048;
    const float4* hi4 = reinterpret_cast<const float4*>(Hi) + (size_t)b * 2048;

    // issue ALL 16 LDG.128 before any STS -> 16 loads in flight per thread
    float4 r[8], m[8];
#pragma unroll
    for (int i = 0; i < 8; i++) r[i] = hr4[(i * 8 + w) * 32 + lane];
#pragma unroll
    for (int i = 0; i < 8; i++) m[i] = hi4[(i * 8 + w) * 32 + lane];
#pragma unroll
    for (int i = 0; i < 8; i++) {
        int base = (i * 8 + w) * 33 + lane;
        S.S[0][base] = r[i].x; S.S[1][base] = r[i].y;
        S.S[2][base] = r[i].z; S.S[3][base] = r[i].w;
        S.S[4][base] = m[i].x; S.S[5][base] = m[i].y;
        S.S[6][base] = m[i].z; S.S[7][base] = m[i].w;
    }
    __syncthreads();

#pragma unroll
    for (int p = 0; p < 2; p++) {
        int idx = t + p * 256;
        int c = idx >> 6, l = idx & 63;
        float s = 0.f;
#pragma unroll
        for (int k = 0; k < 32; k++) s += S.S[c][l * 33 + k];
        float v = s * (1.f / 32.f);
        S.Hmk[idx] = v;
        g_Hmk[(size_t)b * 512 + idx] = v;
    }
    {
        int c = t >> 5, k = t & 31;
        float s = 0.f;
#pragma unroll
        for (int l = 0; l < 64; l++) s += S.S[c][l * 33 + k];
        float v = s * (1.f / 64.f);
        S.Hml[t] = v;
        g_Hml[(size_t)b * 256 + t] = v;
    }
    __syncthreads();

    // layer0 stats (A inputs zero => relu(0.1*P0 @ Hmean))
    int o = t >> 2, q = t & 3;
    float pa[8], pu[8];
#pragma unroll
    for (int c = 0; c < 8; c++) {
        pa[c] = 0.1f * Ph[o * 8 + c];
        pu[c] = 0.1f * Ph[512 + o * 8 + c];
    }
    float ps = 0.f, pss = 0.f;
#pragma unroll
    for (int j = 0; j < 16; j++) {
        int l = q * 16 + j;
        float v = 0.f;
#pragma unroll
        for (int c = 0; c < 8; c++) v += pa[c] * S.Hmk[c * 64 + l];
        v = fmaxf(v, 0.f);
        ps += v; pss += v * v;
    }
    ps += __shfl_xor_sync(0xffffffffu, ps, 1);  ps += __shfl_xor_sync(0xffffffffu, ps, 2);
    pss += __shfl_xor_sync(0xffffffffu, pss, 1); pss += __shfl_xor_sync(0xffffffffu, pss, 2);
    if (q == 0) { atomicAdd(&g_stats[o], ps); atomicAdd(&g_stats[64 + o], pss); }

    float us = 0.f, uss = 0.f;
#pragma unroll
    for (int j = 0; j < 8; j++) {
        int k = q * 8 + j;
        float v = 0.f;
#pragma unroll
        for (int c = 0; c < 8; c++) v += pu[c] * S.Hml[c * 32 + k];
        v = fmaxf(v, 0.f);
        us += v; uss += v * v;
    }
    us += __shfl_xor_sync(0xffffffffu, us, 1);  us += __shfl_xor_sync(0xffffffffu, us, 2);
    uss += __shfl_xor_sync(0xffffffffu, uss, 1); uss += __shfl_xor_sync(0xffffffffu, uss, 2);
    if (q == 0) { atomicAdd(&g_stats[128 + o], us); atomicAdd(&g_stats[192 + o], uss); }
}

// ---------------- K2: recompute layer0 (lazy BN), layer1 GEMMs, relu, stats ----------------
struct __align__(16) SK2 {
    float AP[4096], UE[2048];
    float Pa[512], Pu[512], P0a[512], P0u[512];
    float Hmk[512], Hml[256];
    float Part[8 * 64];
    float ScA[64], ShA[64], ScU[64], ShU[64];
    float MA[64], MU[64], BA[64], BU[64];
};

__global__ void __launch_bounds__(256) k2_full(const float* __restrict__ Ph,
                                               const float* __restrict__ gamma,
                                               const float* __restrict__ beta) {
    extern __shared__ __align__(16) char sraw[];
    SK2& S = *reinterpret_cast<SK2*>(sraw);
    int b = blockIdx.x, t = threadIdx.x;

    if (t < 64) {
        float m = g_stats[t] * (1.f / 65536.f);
        float v = g_stats[64 + t] * (1.f / 65536.f) - m * m;
        float sc = gamma[t] * rsqrtf(v + EPS);
        S.ScA[t] = sc; S.ShA[t] = beta[t] - m * sc;
        float mu = g_stats[128 + t] * (1.f / 32768.f);
        float vu = g_stats[192 + t] * (1.f / 32768.f) - mu * mu;
        float su = gamma[t] * rsqrtf(vu + EPS);
        S.ScU[t] = su; S.ShU[t] = beta[t] - mu * su;
    }
    for (int i = t; i < 512; i += 256) {
        S.Pa[i] = g_TPa[i]; S.Pu[i] = g_TPu[i];
        S.P0a[i] = 0.1f * Ph[i]; S.P0u[i] = 0.1f * Ph[512 + i];
        S.Hmk[i] = g_Hmk[(size_t)b * 512 + i];
    }
    S.Hml[t] = g_Hml[(size_t)b * 256 + t];
    __syncthreads();

    {
        int l = t & 63, og = t >> 6;
#pragma unroll
        for (int j = 0; j < 16; j++) {
            int o = og * 16 + j;
            float r = 0.f;
#pragma unroll
            for (int c = 0; c < 8; c++) r += S.P0a[o * 8 + c] * S.Hmk[c * 64 + l];
            S.AP[o * 64 + l] = fmaxf(r, 0.f) * S.ScA[o] + S.ShA[o];
        }
        int k = t & 31, og2 = t >> 5;
#pragma unroll
        for (int j = 0; j < 8; j++) {
            int o = og2 * 8 + j;
            float r = 0.f;
#pragma unroll
            for (int c = 0; c < 8; c++) r += S.P0u[o * 8 + c] * S.Hml[c * 32 + k];
            S.UE[o * 32 + k] = fmaxf(r, 0.f) * S.ScU[o] + S.ShU[o];
        }
    }
    __syncthreads();

    {
        int o = t >> 2, q = t & 3;
        float s = 0.f;
#pragma unroll
        for (int j = 0; j < 16; j++) s += S.AP[o * 64 + q * 16 + ((o + j) & 15)];
        s += __shfl_xor_sync(0xffffffffu, s, 1); s += __shfl_xor_sync(0xffffffffu, s, 2);
        if (q == 0) S.MA[o] = s * (1.f / 64.f);
        float su = 0.f;
#pragma unroll
        for (int j = 0; j < 8; j++) su += S.UE[o * 32 + q * 8 + ((o + j) & 7)];
        su += __shfl_xor_sync(0xffffffffu, su, 1); su += __shfl_xor_sync(0xffffffffu, su, 2);
        if (q == 0) S.MU[o] = su * (1.f / 32.f);
    }
    __syncthreads();

    {
        int o = t & 63, g = t >> 6;
        float s = 0.f, su = 0.f;
#pragma unroll
        for (int j = 0; j < 16; j++) {
            int c = g * 16 + j;
            s  += g_TQ2a[c * 64 + o] * S.MU[c];
            su += g_TQ2u[c * 64 + o] * S.MA[c];
        }
        S.Part[g * 64 + o] = s;
        S.Part[256 + g * 64 + o] = su;
    }
    __syncthreads();
    if (t < 64) {
        S.BA[t] = S.Part[t] + S.Part[64 + t] + S.Part[128 + t] + S.Part[192 + t];
        S.BU[t] = S.Part[256 + t] + S.Part[320 + t] + S.Part[384 + t] + S.Part[448 + t];
    }
    __syncthreads();

    int o0 = (t >> 4) * 4, l0 = (t & 15) * 4;
    float acc[4][4];
#pragma unroll
    for (int i = 0; i < 4; i++) {
        float bi = S.BA[o0 + i];
#pragma unroll
        for (int j = 0; j < 4; j++) acc[i][j] = bi;
    }
#pragma unroll
    for (int c = 0; c < 8; c++) {
        float4 p = ld4(&S.Pa[c * 64 + o0]);
        float4 h = ld4(&S.Hmk[c * 64 + l0]);
        acc[0][0] += p.x * h.x; acc[0][1] += p.x * h.y; acc[0][2] += p.x * h.z; acc[0][3] += p.x * h.w;
        acc[1][0] += p.y * h.x; acc[1][1] += p.y * h.y; acc[1][2] += p.y * h.z; acc[1][3] += p.y * h.w;
        acc[2][0] += p.z * h.x; acc[2][1] += p.z * h.y; acc[2][2] += p.z * h.z; acc[2][3] += p.z * h.w;
        acc[3][0] += p.w * h.x; acc[3][1] += p.w * h.y; acc[3][2] += p.w * h.z; acc[3][3] += p.w * h.w;
    }
#pragma unroll
    for (int c = 0; c < 64; c++) {
        float4 qv = ld4(&g_TQa[c * 64 + o0]);
        float4 av = ld4(&S.AP[c * 64 + l0]);
        acc[0][0] += qv.x * av.x; acc[0][1] += qv.x * av.y; acc[0][2] += qv.x * av.z; acc[0][3] += qv.x * av.w;
        acc[1][0] += qv.y * av.x; acc[1][1] += qv.y * av.y; acc[1][2] += qv.y * av.z; acc[1][3] += qv.y * av.w;
        acc[2][0] += qv.z * av.x; acc[2][1] += qv.z * av.y; acc[2][2] += qv.z * av.z; acc[2][3] += qv.z * av.w;
        acc[3][0] += qv.w * av.x; acc[3][1] += qv.w * av.y; acc[3][2] += qv.w * av.z; acc[3][3] += qv.w * av.w;
    }

    int ou = (t >> 3) * 2, kq = (t & 7) * 4;
    float au[2][4];
#pragma unroll
    for (int i = 0; i < 2; i++) {
        float bi = S.BU[ou + i];
#pragma unroll
        for (int j = 0; j < 4; j++) au[i][j] = bi;
    }
#pragma unroll
    for (int c = 0; c < 8; c++) {
        float2 p = ld2(&S.Pu[c * 64 + ou]);
        float4 h = ld4(&S.Hml[c * 32 + kq]);
        au[0][0] += p.x * h.x; au[0][1] += p.x * h.y; au[0][2] += p.x * h.z; au[0][3] += p.x * h.w;
        au[1][0] += p.y * h.x; au[1][1] += p.y * h.y; au[1][2] += p.y * h.z; au[1][3] += p.y * h.w;
    }
#pragma unroll
    for (int c = 0; c < 64; c++) {
        float2 qv = ld2(&g_TQu[c * 64 + ou]);
        float4 uv = ld4(&S.UE[c * 32 + kq]);
        au[0][0] += qv.x * uv.x; au[0][1] += qv.x * uv.y; au[0][2] += qv.x * uv.z; au[0][3] += qv.x * uv.w;
        au[1][0] += qv.y * uv.x; au[1][1] += qv.y * uv.y; au[1][2] += qv.y * uv.z; au[1][3] += qv.y * uv.w;
    }

    float sA[4], sAS[4];
#pragma unroll
    for (int i = 0; i < 4; i++) {
        float r0 = fmaxf(acc[i][0], 0.f), r1 = fmaxf(acc[i][1], 0.f);
        float r2 = fmaxf(acc[i][2], 0.f), r3 = fmaxf(acc[i][3], 0.f);
        st4(&g_A1[(size_t)b * 4096 + (o0 + i) * 64 + l0], make_float4(r0, r1, r2, r3));
        sA[i] = r0 + r1 + r2 + r3;
        sAS[i] = r0 * r0 + r1 * r1 + r2 * r2 + r3 * r3;
    }
#pragma unroll
    for (int m = 1; m < 16; m <<= 1) {
#pragma unroll
        for (int i = 0; i < 4; i++) {
            sA[i] += __shfl_xor_sync(0xffffffffu, sA[i], m);
            sAS[i] += __shfl_xor_sync(0xffffffffu, sAS[i], m);
        }
    }
    if ((t & 15) == 0) {
#pragma unroll
        for (int i = 0; i < 4; i++) {
            atomicAdd(&g_stats[256 + o0 + i], sA[i]);
            atomicAdd(&g_stats[320 + o0 + i], sAS[i]);
        }
    }

    float sU[2], sUS[2];
#pragma unroll
    for (int i = 0; i < 2; i++) {
        float r0 = fmaxf(au[i][0], 0.f), r1 = fmaxf(au[i][1], 0.f);
        float r2 = fmaxf(au[i][2], 0.f), r3 = fmaxf(au[i][3], 0.f);
        sU[i] = r0 + r1 + r2 + r3;
        sUS[i] = r0 * r0 + r1 * r1 + r2 * r2 + r3 * r3;
    }
#pragma unroll
    for (int m = 1; m < 8; m <<= 1) {
#pragma unroll
        for (int i = 0; i < 2; i++) {
            sU[i] += __shfl_xor_sync(0xffffffffu, sU[i], m);
            sUS[i] += __shfl_xor_sync(0xffffffffu, sUS[i], m);
        }
    }
    if ((t & 7) == 0) {
#pragma unroll
        for (int i = 0; i < 2; i++) {
            atomicAdd(&g_stats[384 + ou + i], sU[i]);
            atomicAdd(&g_stats[448 + ou + i], sUS[i]);
            g_U1m[(size_t)b * 64 + ou + i] = sU[i] * (1.f / 32.f);
        }
    }
}

// ---------------- K3: output layer + per-k norm + fused Vhat*Phat stream ----------------
__global__ void __launch_bounds__(256) k3_fused(const float* __restrict__ gamma,
                                                const float* __restrict__ beta,
                                                const float* __restrict__ Vh,
                                                float* __restrict__ out) {
    __shared__ float sAP[4096];          // normalized layer1 AP [c][l]
    __shared__ float sPo[256];
    __shared__ float sHmk[512];
    __shared__ float sV[32 * 65];
    __shared__ float sPb[8 * 32];
    __shared__ float sMU[64], sB[32], sFac[32], sScA[64], sShA[64];
    int b = blockIdx.x, t = threadIdx.x;

    // prefetch raw A1 into registers
    float a_raw[16];
#pragma unroll
    for (int j = 0; j < 16; j++) a_raw[j] = g_A1[(size_t)b * 4096 + t + j * 256];

    if (t < 64) {
        float m = g_stats[256 + t] * (1.f / 65536.f);
        float v = g_stats[320 + t] * (1.f / 65536.f) - m * m;
        float sc = gamma[64 + t] * rsqrtf(v + EPS);
        sScA[t] = sc; sShA[t] = beta[64 + t] - m * sc;
        float mu = g_stats[384 + t] * (1.f / 32768.f);
        float vu = g_stats[448 + t] * (1.f / 32768.f) - mu * mu;
        float su = gamma[64 + t] * rsqrtf(vu + EPS);
        float sh = beta[64 + t] - mu * su;
        sMU[t] = g_U1m[(size_t)b * 64 + t] * su + sh;
    }
    sPo[t] = g_TPo[t];
    for (int i = t; i < 512; i += 256) sHmk[i] = g_Hmk[(size_t)b * 512 + i];
    __syncthreads();

#pragma unroll
    for (int j = 0; j < 16; j++) {
        int i = t + j * 256;
        int c = i >> 6;
        sAP[i] = a_raw[j] * sScA[c] + sShA[c];
    }
    {
        int k = t & 31, g = t >> 5;
        float s = 0.f;
#pragma unroll
        for (int j = 0; j < 8; j++) {
            int c = g * 8 + j;
            s += g_TQo2[c * 32 + k] * sMU[c];
        }
        sPb[g * 32 + k] = s;
    }
    __syncthreads();
    if (t < 32) {
        float s = 0.f;
#pragma unroll
        for (int g = 0; g < 8; g++) s += sPb[g * 32 + t];
        sB[t] = s;
    }
    __syncthreads();

    // GEMM 32(k) x 64(l) x 72: thread tile 4(k) x 2(l)
    int ko = (t >> 5) * 4, lo = (t & 31) * 2;
    float acc[4][2];
#pragma unroll
    for (int i = 0; i < 4; i++) { acc[i][0] = sB[ko + i]; acc[i][1] = sB[ko + i]; }
#pragma unroll
    for (int c = 0; c < 8; c++) {
        float4 p = ld4(&sPo[c * 32 + ko]);
        float h0 = sHmk[c * 64 + lo], h1 = sHmk[c * 64 + lo + 1];
        acc[0][0] += p.x * h0; acc[0][1] += p.x * h1;
        acc[1][0] += p.y * h0; acc[1][1] += p.y * h1;
        acc[2][0] += p.z * h0; acc[2][1] += p.z * h1;
        acc[3][0] += p.w * h0; acc[3][1] += p.w * h1;
    }
#pragma unroll
    for (int c = 0; c < 64; c++) {
        float4 qv = ld4(&g_TQo[c * 32 + ko]);
        float2 a = ld2(&sAP[c * 64 + lo]);
        acc[0][0] += qv.x * a.x; acc[0][1] += qv.x * a.y;
        acc[1][0] += qv.y * a.x; acc[1][1] += qv.y * a.y;
        acc[2][0] += qv.z * a.x; acc[2][1] += qv.z * a.y;
        acc[3][0] += qv.w * a.x; acc[3][1] += qv.w * a.y;
    }
#pragma unroll
    for (int i = 0; i < 4; i++) {
        sV[(ko + i) * 65 + lo] = acc[i][0];
        sV[(ko + i) * 65 + lo + 1] = acc[i][1];
    }
    __syncthreads();

    // norm: 8 lanes per k, shuffle reduce
    {
        int k = t >> 3, j = t & 7;
        float ss = 0.f;
#pragma unroll
        for (int i = 0; i < 8; i++) {
            float x = sV[k * 65 + j * 8 + i];
            ss += x * x;
        }
        ss += __shfl_xor_sync(0xffffffffu, ss, 1);
        ss += __shfl_xor_sync(0xffffffffu, ss, 2);
        ss += __shfl_xor_sync(0xffffffffu, ss, 4);
        if (j == 0) sFac[k] = 8.f * rsqrtf(ss);
    }
    __syncthreads();

    // fused stream with full MLP: batch-load all 8 float4 of Vhat, then scale+store
    const float4* v4 = reinterpret_cast<const float4*>(Vh) + (size_t)b * 2048;
    float4* o4 = reinterpret_cast<float4*>(out) + (size_t)b * 2048;
    float4 v[8];
#pragma unroll
    for (int j = 0; j < 8; j++) v[j] = v4[t + j * 256];
#pragma unroll
    for (int j = 0; j < 8; j++) {
        int i = t + j * 256;
        int l = i >> 5, k = i & 31;
        float pf = sV[k * 65 + l] * sFac[k];
        v[j].x *= pf; v[j].y *= pf; v[j].z *= pf; v[j].w *= pf;
        o4[i] = v[j];
    }
}

// ---------------- host ----------------
extern "C" void kernel_launch(void* const* d_in, const int* in_sizes, int n_in,
                              void* d_out, int out_size) {
    (void)in_sizes; (void)n_in; (void)out_size;
    const float* Hr = (const float*)d_in[0];
    const float* Hi = (const float*)d_in[1];
    const float* Vh = (const float*)d_in[2];
    const float* Qh = (const float*)d_in[3];
    const float* Ph = (const float*)d_in[4];
    const float* Qo = (const float*)d_in[5];
    const float* Po = (const float*)d_in[6];
    const float* gamma = (const float*)d_in[7];
    const float* beta = (const float*)d_in[8];

    static int attr_done = 0;
    if (!attr_done) {
        cudaFuncSetAttribute(k1_l0, cudaFuncAttributeMaxDynamicSharedMemorySize, (int)sizeof(SK1));
        cudaFuncSetAttribute(k2_full, cudaFuncAttributeMaxDynamicSharedMemorySize, (int)sizeof(SK2));
        attr_done = 1;
    }

    k0_prep<<<16, 256>>>(Qh, Ph, Qo, Po);
    k1_l0<<<1024, 256, sizeof(SK1)>>>(Hr, Hi, Ph);
    k2_full<<<1024, 256, sizeof(SK2)>>>(Ph, gamma, beta);
    k3_fused<<<1024, 256>>>(gamma, beta, Vh, (float*)d_out);
}